// round 14
// baseline (speedup 1.0000x reference)
#include <cuda_runtime.h>
#include <cuda_bf16.h>
#include <cstdint>

#define VOCAB  8000
#define HID    256
#define BATCH  32
#define SEQ    256
#define NTOK   (BATCH * SEQ)          // 8192
#define OUT_ROWS NTOK                 // 8192
#define KQ     768                    // folded int8 K: [q1|q1|q2] / [q1|q2|q1]

// ---------------- device scratch (no allocation allowed) ----------------
__device__ float g_WihT[VOCAB * HID];
__device__ float g_xp  [NTOK * HID];
__device__ float g_Y   [NTOK * HID];
__device__ __align__(128) int8_t g_A3[NTOK * KQ];    // 6.3 MB
__device__ __align__(128) int8_t g_B3[VOCAB * KQ];   // 6.1 MB

extern __shared__ __align__(1024) char dsmem[];

// ---------------- helpers ----------------------------------------------
__device__ __forceinline__ void ffma2(unsigned long long &d,
                                      unsigned long long a,
                                      unsigned long long b) {
    asm("fma.rn.f32x2 %0, %1, %2, %0;" : "+l"(d) : "l"(a), "l"(b));
}
__device__ __forceinline__ unsigned long long pack2(float lo, float hi) {
    unsigned long long r;
    asm("mov.b64 %0, {%1, %2};" : "=l"(r) : "f"(lo), "f"(hi));
    return r;
}
__device__ __forceinline__ float2 unpack2(unsigned long long v) {
    float2 f;
    asm("mov.b64 {%0, %1}, %2;" : "=f"(f.x), "=f"(f.y) : "l"(v));
    return f;
}
__device__ __forceinline__ uint32_t smem_u32(const void* p) {
    uint32_t a;
    asm("{ .reg .u64 t; cvta.to.shared.u64 t, %1; cvt.u32.u64 %0, t; }"
        : "=r"(a) : "l"(p));
    return a;
}

#define CP_ASYNC16(smem, gmem)                                               \
    asm volatile("cp.async.cg.shared.global [%0], [%1], 16;"                 \
                 :: "r"(smem), "l"(gmem))
#define CP_COMMIT() asm volatile("cp.async.commit_group;" ::: "memory")
#define CP_WAIT0()  asm volatile("cp.async.wait_group 0;" ::: "memory")

#define LDSM_X4(r, addr)                                                     \
    asm volatile("ldmatrix.sync.aligned.m8n8.x4.shared.b16 "                 \
                 "{%0,%1,%2,%3}, [%4];"                                      \
                 : "=r"((r)[0]), "=r"((r)[1]), "=r"((r)[2]), "=r"((r)[3])    \
                 : "r"(addr))

#define IMMA16832(d, a, b0, b1)                                              \
    asm volatile("mma.sync.aligned.m16n8k32.row.col.s32.s8.s8.s32 "          \
                 "{%0,%1,%2,%3}, {%4,%5,%6,%7}, {%8,%9}, {%0,%1,%2,%3};"     \
                 : "+r"((d)[0]), "+r"((d)[1]), "+r"((d)[2]), "+r"((d)[3])    \
                 : "r"((a)[0]), "r"((a)[1]), "r"((a)[2]), "r"((a)[3]),       \
                   "r"(b0), "r"(b1))

// ---------------- K1: transpose W_ih ------------------------------------
__global__ void transpose_wih(const float* __restrict__ W, float* __restrict__ WT) {
    __shared__ float tile[32][33];
    int v = blockIdx.x * 32 + threadIdx.x;
    int h = blockIdx.y * 32 + threadIdx.y;
    tile[threadIdx.y][threadIdx.x] = W[h * VOCAB + v];
    __syncthreads();
    int v2 = blockIdx.x * 32 + threadIdx.y;
    int h2 = blockIdx.y * 32 + threadIdx.x;
    WT[v2 * HID + h2] = tile[threadIdx.x][threadIdx.y];
}

// ---------------- K2: gather + b_ih -------------------------------------
__global__ void gather_emb(const int* __restrict__ X,
                           const float* __restrict__ bih,
                           const float* __restrict__ WT,
                           float* __restrict__ xp) {
    int tb = blockIdx.x;
    int h  = threadIdx.x;
    int t  = tb >> 5;
    int b  = tb & 31;
    int x  = X[b * SEQ + t];
    xp[tb * HID + h] = WT[x * HID + h] + bih[h];
}

// ---------------- K3: recurrence (EXACT round-6 proven version) ---------
#define KREG 192
#define KSM  64
#define RNN_SMEM ((HID + HID * 65) * (int)sizeof(float))

__global__ __launch_bounds__(256, 1)
void rnn_recurrence(const float* __restrict__ h0,
                    const float* __restrict__ W_hh,
                    const float* __restrict__ b_hh,
                    const float* __restrict__ xp,
                    float* __restrict__ Y,
                    float* __restrict__ h_last) {
    float* smem = (float*)dsmem;
    float* sh_h = smem;
    float* sh_w = smem + HID;

    const int j = threadIdx.x;
    const int b = blockIdx.x;

    unsigned long long wp[96];
    {
        const float2* wrow = (const float2*)(W_hh + j * HID);
        #pragma unroll
        for (int i = 0; i < 96; i++) {
            float2 w = wrow[i];
            wp[i] = pack2(w.x, w.y);
        }
    }
    for (int idx = j; idx < HID * KSM; idx += 256) {
        int jj = idx >> 6, kk = idx & 63;
        sh_w[jj * 65 + kk] = W_hh[jj * HID + KREG + kk];
    }
    sh_h[j] = h0[b * HID + j];
    const float bh = b_hh[j];
    __syncthreads();

    const float* wsr = sh_w + j * 65;

    for (int t = 0; t < SEQ; t++) {
        float xv = xp[(t * BATCH + b) * HID + j];
        unsigned long long acc2 = 0ULL;
        const ulonglong2* hp = (const ulonglong2*)sh_h;
        #pragma unroll
        for (int i = 0; i < 24; i++) {
            ulonglong2 q0 = hp[2 * i];
            ulonglong2 q1 = hp[2 * i + 1];
            ffma2(acc2, q0.x, wp[4 * i + 0]);
            ffma2(acc2, q0.y, wp[4 * i + 1]);
            ffma2(acc2, q1.x, wp[4 * i + 2]);
            ffma2(acc2, q1.y, wp[4 * i + 3]);
        }
        float2 s = unpack2(acc2);
        float acc = s.x + s.y + xv + bh;

        #pragma unroll
        for (int kk = 0; kk < KSM; kk += 4) {
            float4 hq = *(const float4*)(sh_h + KREG + kk);
            acc += hq.x * wsr[kk + 0];
            acc += hq.y * wsr[kk + 1];
            acc += hq.z * wsr[kk + 2];
            acc += hq.w * wsr[kk + 3];
        }
        float hn = tanhf(acc);

        __syncthreads();
        sh_h[j] = hn;
        Y[(t * BATCH + b) * HID + j] = hn;
        if (t == SEQ - 1) h_last[b * HID + j] = hn;
        __syncthreads();
    }
}

// ---------------- K4a/K4b: int8 2-level quantization --------------------
// A3 row: [q1(256) | q1(256) | q2(256)]  (Y, scale 127 then 254)
// B3 row: [q1(256) | q2(256) | q1(256)]  (W_out, scale 2032 then 254)
__global__ void quant_A(const float* __restrict__ Y, int8_t* __restrict__ A3) {
    int idx = blockIdx.x * 256 + threadIdx.x;
    int m = idx >> 8, k = idx & 255;
    float f = Y[m * HID + k] * 127.0f;
    int q1 = __float2int_rn(f);
    int q2 = __float2int_rn((f - (float)q1) * 254.0f);
    int8_t* row = A3 + (size_t)m * KQ;
    row[k]       = (int8_t)q1;
    row[256 + k] = (int8_t)q1;
    row[512 + k] = (int8_t)q2;
}

__global__ void quant_B(const float* __restrict__ W, int8_t* __restrict__ B3) {
    int idx = blockIdx.x * 256 + threadIdx.x;
    int n = idx >> 8, k = idx & 255;
    float f = W[n * HID + k] * 2032.0f;
    int q1 = __float2int_rn(f);
    int q2 = __float2int_rn((f - (float)q1) * 254.0f);
    int8_t* row = B3 + (size_t)n * KQ;
    row[k]       = (int8_t)q1;
    row[256 + k] = (int8_t)q2;
    row[512 + k] = (int8_t)q1;
}

// ---------------- K5: int8 IMMA GEMM, tile 128x64, K=768 folded ---------
// acc1 (chunks 0-3)  = q1A*q1B          weight 1/(127*2032)
// acc2 (chunks 4-11) = q1A*q2B + q2A*q1B weight 1/(127*2032*254)
#define QBK     64
#define QSTRIDE 80                       // bytes/row in smem (64 + 16 pad)
#define QA_B    (128 * QSTRIDE)          // 10240
#define QSTAGE  (QA_B + 64 * QSTRIDE)    // 15360
#define QGEMM_SMEM (2 * QSTAGE)          // 30720

__global__ __launch_bounds__(256, 2)
void out_gemm_imma(const int8_t* __restrict__ A3,
                   const int8_t* __restrict__ B3,
                   const float* __restrict__ bias,
                   float* __restrict__ C) {
    const uint32_t sbase = smem_u32(dsmem);
    const int tid = threadIdx.x, wid = tid >> 5, l = tid & 31;
    const int wm = wid & 3, wn = wid >> 2;          // 4x2 warps -> 32x32 each
    const int m0 = blockIdx.x * 128, n0 = blockIdx.y * 64;

    // fill mapping: 16B chunks; A: 512 chunks (2/thr), B: 256 (1/thr)
    const int rA = tid >> 2, cA = (tid & 3) * 16;
    const int8_t* gA0 = A3 + (size_t)(m0 + rA) * KQ + cA;
    const int8_t* gA1 = gA0 + (size_t)64 * KQ;
    const int8_t* gB0 = B3 + (size_t)(n0 + (tid >> 2 & 63)) * KQ + cA;
    const uint32_t sA0 = rA * QSTRIDE + cA;
    const uint32_t sA1 = sA0 + 64 * QSTRIDE;
    const uint32_t sB0 = QA_B + (tid >> 2 & 63) * QSTRIDE + cA;

    // ldmatrix per-thread offsets (bytes)
    const uint32_t offA = (wm * 32 + (l & 15)) * QSTRIDE + ((l >> 4) & 1) * 16;
    const uint32_t offB = QA_B +
        (wn * 32 + (l & 7) + ((l >> 4) & 1) * 8) * QSTRIDE + ((l >> 3) & 1) * 16;

    int acc1[2][4][4], acc2[2][4][4];
    #pragma unroll
    for (int mb = 0; mb < 2; mb++)
        #pragma unroll
        for (int nb = 0; nb < 4; nb++)
            #pragma unroll
            for (int q = 0; q < 4; q++) { acc1[mb][nb][q] = 0; acc2[mb][nb][q] = 0; }

    // prologue: stage 0 = K-chunk 0
    CP_ASYNC16(sbase + sA0, gA0);
    CP_ASYNC16(sbase + sA1, gA1);
    CP_ASYNC16(sbase + sB0, gB0);
    CP_COMMIT();

    for (int it = 0; it < KQ / QBK; it++) {         // 12 chunks
        const int s = it & 1;
        CP_WAIT0();
        __syncthreads();
        if (it + 1 < KQ / QBK) {
            const uint32_t nbse = sbase + ((it + 1) & 1) * QSTAGE;
            const int ko = (it + 1) * QBK;
            CP_ASYNC16(nbse + sA0, gA0 + ko);
            CP_ASYNC16(nbse + sA1, gA1 + ko);
            CP_ASYNC16(nbse + sB0, gB0 + ko);
            CP_COMMIT();
        }

        int (*acc)[4][4] = (it < 4) ? acc1 : acc2;
        const uint32_t aS = sbase + s * QSTAGE + offA;
        const uint32_t bS = sbase + s * QSTAGE + offB;
        #pragma unroll
        for (int ks = 0; ks < 2; ks++) {            // 2 x k32 per chunk
            uint32_t ra[2][4], rb[2][4];
            LDSM_X4(ra[0], aS + ks * 32);
            LDSM_X4(ra[1], aS + ks * 32 + 16 * QSTRIDE);
            LDSM_X4(rb[0], bS + ks * 32);
            LDSM_X4(rb[1], bS + ks * 32 + 16 * QSTRIDE);
            #pragma unroll
            for (int mb = 0; mb < 2; mb++)
                #pragma unroll
                for (int nb = 0; nb < 4; nb++)
                    IMMA16832(acc[mb][nb], ra[mb],
                              rb[nb >> 1][(nb & 1) * 2],
                              rb[nb >> 1][(nb & 1) * 2 + 1]);
        }
        __syncthreads();
    }

    // epilogue: C = acc1*C1 + acc2*C2 + bias
    const float C1f = 1.0f / 258064.0f;             // 1/(127*2032)
    const float C2f = C1f / 254.0f;
    const int g = l >> 2, t4 = l & 3;
    #pragma unroll
    for (int mb = 0; mb < 2; mb++) {
        int r0 = m0 + wm * 32 + mb * 16 + g;
        float* c0 = C + (size_t)r0 * VOCAB;
        float* c1 = C + (size_t)(r0 + 8) * VOCAB;
        #pragma unroll
        for (int nb = 0; nb < 4; nb++) {
            int col = n0 + wn * 32 + nb * 8 + 2 * t4;
            float2 bv = *(const float2*)(bias + col);
            float2 o0, o1;
            o0.x = (float)acc1[mb][nb][0] * C1f + (float)acc2[mb][nb][0] * C2f + bv.x;
            o0.y = (float)acc1[mb][nb][1] * C1f + (float)acc2[mb][nb][1] * C2f + bv.y;
            o1.x = (float)acc1[mb][nb][2] * C1f + (float)acc2[mb][nb][2] * C2f + bv.x;
            o1.y = (float)acc1[mb][nb][3] * C1f + (float)acc2[mb][nb][3] * C2f + bv.y;
            *(float2*)(c0 + col) = o0;
            *(float2*)(c1 + col) = o1;
        }
    }
}

// ---------------- launch ------------------------------------------------
extern "C" void kernel_launch(void* const* d_in, const int* in_sizes, int n_in,
                              void* d_out, int out_size) {
    const int*   X     = (const int*)  d_in[0];
    const float* h0    = (const float*)d_in[1];
    const float* W_ih  = (const float*)d_in[2];
    const float* b_ih  = (const float*)d_in[3];
    const float* W_hh  = (const float*)d_in[4];
    const float* b_hh  = (const float*)d_in[5];
    const float* W_out = (const float*)d_in[6];
    const float* b_out = (const float*)d_in[7];
    float* out    = (float*)d_out;
    float* h_last = (float*)d_out + (out_size - BATCH * HID);

    float* WihT; cudaGetSymbolAddress((void**)&WihT, g_WihT);
    float* xp;   cudaGetSymbolAddress((void**)&xp,   g_xp);
    float* Y;    cudaGetSymbolAddress((void**)&Y,    g_Y);
    int8_t* A3;  cudaGetSymbolAddress((void**)&A3,   g_A3);
    int8_t* B3;  cudaGetSymbolAddress((void**)&B3,   g_B3);

    cudaFuncSetAttribute(rnn_recurrence,
                         cudaFuncAttributeMaxDynamicSharedMemorySize, RNN_SMEM);
    cudaFuncSetAttribute(out_gemm_imma,
                         cudaFuncAttributeMaxDynamicSharedMemorySize, QGEMM_SMEM);

    transpose_wih<<<dim3(VOCAB / 32, HID / 32), dim3(32, 32)>>>(W_ih, WihT);
    gather_emb<<<NTOK, HID>>>(X, b_ih, WihT, xp);
    quant_B<<<(VOCAB * HID) / 256, 256>>>(W_out, B3);
    rnn_recurrence<<<BATCH, HID, RNN_SMEM>>>(h0, W_hh, b_hh, xp, Y, h_last);
    quant_A<<<(NTOK * HID) / 256, 256>>>(Y, A3);
    out_gemm_imma<<<dim3(OUT_ROWS / 128, VOCAB / 64), 256, QGEMM_SMEM>>>(
        A3, B3, b_out, out);
}

// round 16
// speedup vs baseline: 1.5386x; 1.5386x over previous
#include <cuda_runtime.h>
#include <cuda_bf16.h>
#include <cstdint>

#define VOCAB  8000
#define HID    256
#define BATCH  32
#define SEQ    256
#define NTOK   (BATCH * SEQ)          // 8192
#define OUT_ROWS NTOK                 // 8192
#define NPAD   8064                   // 63 * 128, zero-padded W_out rows
#define KTOT   768                    // [hi | lo | hi] x 256
#define NCHUNK 4
#define TCH    (SEQ / NCHUNK)         // 64 timesteps per chunk
#define MCH    (TCH * BATCH)          // 2048 rows per chunk

// ---------------- device scratch (no allocation allowed) ----------------
__device__ float g_WihT[VOCAB * HID];
__device__ float g_xp  [NTOK * HID];
__device__ float g_Y   [NTOK * HID];
__device__ float g_h   [BATCH * HID];
__device__ __align__(128) __nv_bfloat16 g_A2[NTOK * KTOT];   // 12.6 MB
__device__ __align__(128) __nv_bfloat16 g_B2[NPAD * KTOT];   // 12.4 MB

extern __shared__ __align__(1024) char dsmem[];

// ---------------- helpers ----------------------------------------------
__device__ __forceinline__ void ffma2(unsigned long long &d,
                                      unsigned long long a,
                                      unsigned long long b) {
    asm("fma.rn.f32x2 %0, %1, %2, %0;" : "+l"(d) : "l"(a), "l"(b));
}
__device__ __forceinline__ unsigned long long pack2(float lo, float hi) {
    unsigned long long r;
    asm("mov.b64 %0, {%1, %2};" : "=l"(r) : "f"(lo), "f"(hi));
    return r;
}
__device__ __forceinline__ float2 unpack2(unsigned long long v) {
    float2 f;
    asm("mov.b64 {%0, %1}, %2;" : "=f"(f.x), "=f"(f.y) : "l"(v));
    return f;
}
__device__ __forceinline__ uint32_t smem_u32(const void* p) {
    uint32_t a;
    asm("{ .reg .u64 t; cvta.to.shared.u64 t, %1; cvt.u32.u64 %0, t; }"
        : "=r"(a) : "l"(p));
    return a;
}

#define CP_ASYNC16(smem, gmem)                                               \
    asm volatile("cp.async.cg.shared.global [%0], [%1], 16;"                 \
                 :: "r"(smem), "l"(gmem))
#define CP_COMMIT() asm volatile("cp.async.commit_group;" ::: "memory")
#define CP_WAIT0()  asm volatile("cp.async.wait_group 0;" ::: "memory")

#define LDSM_X4(r, addr)                                                     \
    asm volatile("ldmatrix.sync.aligned.m8n8.x4.shared.b16 "                 \
                 "{%0,%1,%2,%3}, [%4];"                                      \
                 : "=r"((r)[0]), "=r"((r)[1]), "=r"((r)[2]), "=r"((r)[3])    \
                 : "r"(addr))

#define MMA16816(d, a, b0, b1)                                               \
    asm volatile("mma.sync.aligned.m16n8k16.row.col.f32.bf16.bf16.f32 "      \
                 "{%0,%1,%2,%3}, {%4,%5,%6,%7}, {%8,%9}, {%0,%1,%2,%3};"     \
                 : "+f"((d)[0]), "+f"((d)[1]), "+f"((d)[2]), "+f"((d)[3])    \
                 : "r"((a)[0]), "r"((a)[1]), "r"((a)[2]), "r"((a)[3]),       \
                   "r"(b0), "r"(b1))

// ---------------- K1: transpose W_ih ------------------------------------
__global__ void transpose_wih(const float* __restrict__ W, float* __restrict__ WT) {
    __shared__ float tile[32][33];
    int v = blockIdx.x * 32 + threadIdx.x;
    int h = blockIdx.y * 32 + threadIdx.y;
    tile[threadIdx.y][threadIdx.x] = W[h * VOCAB + v];
    __syncthreads();
    int v2 = blockIdx.x * 32 + threadIdx.y;
    int h2 = blockIdx.y * 32 + threadIdx.x;
    WT[v2 * HID + h2] = tile[threadIdx.x][threadIdx.y];
}

// ---------------- K2: gather + b_ih -------------------------------------
__global__ void gather_emb(const int* __restrict__ X,
                           const float* __restrict__ bih,
                           const float* __restrict__ WT,
                           float* __restrict__ xp) {
    int tb = blockIdx.x;
    int h  = threadIdx.x;
    int t  = tb >> 5;
    int b  = tb & 31;
    int x  = X[b * SEQ + t];
    xp[tb * HID + h] = WT[x * HID + h] + bih[h];
}

__global__ void init_h(const float* __restrict__ h0, float* __restrict__ hs) {
    hs[blockIdx.x * HID + threadIdx.x] = h0[blockIdx.x * HID + threadIdx.x];
}
__global__ void copy_hlast(const float* __restrict__ hs, float* __restrict__ hl) {
    hl[blockIdx.x * HID + threadIdx.x] = hs[blockIdx.x * HID + threadIdx.x];
}

// ---------------- K3: recurrence chunk (R6 core, 64 steps) --------------
#define KREG 192
#define KSM  64
#define RNN_SMEM ((HID + HID * 65) * (int)sizeof(float))

__global__ __launch_bounds__(256, 1)
void rnn_chunk(float* __restrict__ hstate,
               const float* __restrict__ W_hh,
               const float* __restrict__ b_hh,
               const float* __restrict__ xp,
               float* __restrict__ Y,
               int t0) {
    float* smem = (float*)dsmem;
    float* sh_h = smem;
    float* sh_w = smem + HID;

    const int j = threadIdx.x;
    const int b = blockIdx.x;

    unsigned long long wp[96];
    {
        const float2* wrow = (const float2*)(W_hh + j * HID);
        #pragma unroll
        for (int i = 0; i < 96; i++) {
            float2 w = wrow[i];
            wp[i] = pack2(w.x, w.y);
        }
    }
    for (int idx = j; idx < HID * KSM; idx += 256) {
        int jj = idx >> 6, kk = idx & 63;
        sh_w[jj * 65 + kk] = W_hh[jj * HID + KREG + kk];
    }
    sh_h[j] = hstate[b * HID + j];
    const float bh = b_hh[j];
    __syncthreads();

    const float* wsr = sh_w + j * 65;

    for (int tt = 0; tt < TCH; tt++) {
        const int t = t0 + tt;
        float xv = xp[(t * BATCH + b) * HID + j];
        unsigned long long acc2 = 0ULL;
        const ulonglong2* hp = (const ulonglong2*)sh_h;
        #pragma unroll
        for (int i = 0; i < 24; i++) {
            ulonglong2 q0 = hp[2 * i];
            ulonglong2 q1 = hp[2 * i + 1];
            ffma2(acc2, q0.x, wp[4 * i + 0]);
            ffma2(acc2, q0.y, wp[4 * i + 1]);
            ffma2(acc2, q1.x, wp[4 * i + 2]);
            ffma2(acc2, q1.y, wp[4 * i + 3]);
        }
        float2 s = unpack2(acc2);
        float acc = s.x + s.y + xv + bh;

        #pragma unroll
        for (int kk = 0; kk < KSM; kk += 4) {
            float4 hq = *(const float4*)(sh_h + KREG + kk);
            acc += hq.x * wsr[kk + 0];
            acc += hq.y * wsr[kk + 1];
            acc += hq.z * wsr[kk + 2];
            acc += hq.w * wsr[kk + 3];
        }
        float hn = tanhf(acc);

        __syncthreads();
        sh_h[j] = hn;
        Y[(t * BATCH + b) * HID + j] = hn;
        __syncthreads();
    }
    hstate[b * HID + j] = sh_h[j];
}

// ---------------- K4a/K4b: bf16 hi/lo split, K-folded layout ------------
__global__ void split_A(const float* __restrict__ Y,
                        __nv_bfloat16* __restrict__ A2, int rowbase) {
    int idx = blockIdx.x * 256 + threadIdx.x;
    int m = rowbase + (idx >> 8), k = idx & 255;
    float y = Y[m * HID + k];
    __nv_bfloat16 hi = __float2bfloat16_rn(y);
    __nv_bfloat16 lo = __float2bfloat16_rn(y - __bfloat162float(hi));
    __nv_bfloat16* row = A2 + (size_t)m * KTOT;
    row[k]       = hi;
    row[256 + k] = lo;
    row[512 + k] = hi;
}

__global__ void split_B(const float* __restrict__ W,
                        __nv_bfloat16* __restrict__ B2) {
    int idx = blockIdx.x * 256 + threadIdx.x;
    int n = idx >> 8, k = idx & 255;
    float y = (n < VOCAB) ? W[n * HID + k] : 0.f;
    __nv_bfloat16 hi = __float2bfloat16_rn(y);
    __nv_bfloat16 lo = __float2bfloat16_rn(y - __bfloat162float(hi));
    __nv_bfloat16* row = B2 + (size_t)n * KTOT;
    row[k]       = hi;
    row[256 + k] = hi;
    row[512 + k] = lo;
}

// ---------------- K5: bf16 HMMA GEMM (R6 proven, M-chunked) -------------
#define BK       64
#define ASTRIDE  72
#define STAGE_B  (128 * ASTRIDE * 2)
#define GEMM_SMEM (4 * STAGE_B)

__global__ __launch_bounds__(256, 2)
void out_gemm_mma(const __nv_bfloat16* __restrict__ A2,
                  const __nv_bfloat16* __restrict__ B2,
                  const float* __restrict__ bias,
                  float* __restrict__ C, int mbase) {
    const uint32_t sbase = smem_u32(dsmem);
    const int tid = threadIdx.x, wid = tid >> 5, l = tid & 31;
    const int wm = wid & 3, wn = wid >> 2;
    const int m0 = mbase + blockIdx.x * 128, n0 = blockIdx.y * 128;

    const uint32_t smA = sbase;
    const uint32_t smB = sbase + 2 * STAGE_B;

    const int lrow = tid >> 1;
    const int lc   = (tid & 1) * 4;
    const __nv_bfloat16* gA = A2 + (size_t)(m0 + lrow) * KTOT + lc * 8;
    const __nv_bfloat16* gB = B2 + (size_t)(n0 + lrow) * KTOT + lc * 8;
    const uint32_t sA = smA + (lrow * ASTRIDE + lc * 8) * 2;
    const uint32_t sB = smB + (lrow * ASTRIDE + lc * 8) * 2;

    const uint32_t offA = ((wm * 32 + (l & 15)) * ASTRIDE + ((l >> 4) & 1) * 8) * 2;
    const uint32_t offB = ((wn * 64 + (l & 7) + ((l >> 4) & 1) * 8) * ASTRIDE +
                           ((l >> 3) & 1) * 8) * 2;

    float acc[2][8][4];
    #pragma unroll
    for (int mb = 0; mb < 2; mb++)
        #pragma unroll
        for (int nb = 0; nb < 8; nb++)
            #pragma unroll
            for (int q = 0; q < 4; q++) acc[mb][nb][q] = 0.f;

    #pragma unroll
    for (int i = 0; i < 4; i++) {
        CP_ASYNC16(sA + i * 16, gA + i * 8);
        CP_ASYNC16(sB + i * 16, gB + i * 8);
    }
    CP_COMMIT();

    for (int it = 0; it < KTOT / BK; it++) {
        const int s = it & 1;
        CP_WAIT0();
        __syncthreads();
        if (it + 1 < KTOT / BK) {
            const int s2 = (it + 1) & 1;
            const __nv_bfloat16* ga = gA + (it + 1) * BK;
            const __nv_bfloat16* gb = gB + (it + 1) * BK;
            #pragma unroll
            for (int i = 0; i < 4; i++) {
                CP_ASYNC16(sA + s2 * STAGE_B + i * 16, ga + i * 8);
                CP_ASYNC16(sB + s2 * STAGE_B + i * 16, gb + i * 8);
            }
            CP_COMMIT();
        }

        const uint32_t aS = smA + s * STAGE_B + offA;
        const uint32_t bS = smB + s * STAGE_B + offB;
        #pragma unroll
        for (int ks = 0; ks < 4; ks++) {
            uint32_t ra0[4], ra1[4], rb[4][4];
            LDSM_X4(ra0, aS + ks * 32);
            LDSM_X4(ra1, aS + ks * 32 + 16 * ASTRIDE * 2);
            #pragma unroll
            for (int p = 0; p < 4; p++)
                LDSM_X4(rb[p], bS + ks * 32 + p * 16 * ASTRIDE * 2);
            #pragma unroll
            for (int nb = 0; nb < 8; nb++) {
                uint32_t b0 = rb[nb >> 1][(nb & 1) * 2];
                uint32_t b1 = rb[nb >> 1][(nb & 1) * 2 + 1];
                MMA16816(acc[0][nb], ra0, b0, b1);
                MMA16816(acc[1][nb], ra1, b0, b1);
            }
        }
        __syncthreads();
    }

    const int g = l >> 2, t4 = l & 3;
    #pragma unroll
    for (int mb = 0; mb < 2; mb++) {
        int row = m0 + wm * 32 + mb * 16 + g;
        float* c0 = C + (size_t)row * VOCAB;
        float* c1 = C + (size_t)(row + 8) * VOCAB;
        #pragma unroll
        for (int nb = 0; nb < 8; nb++) {
            int col = n0 + wn * 64 + nb * 8 + 2 * t4;
            if (col < VOCAB) {
                float2 bv = *(const float2*)(bias + col);
                float2 o0 = { acc[mb][nb][0] + bv.x, acc[mb][nb][1] + bv.y };
                float2 o1 = { acc[mb][nb][2] + bv.x, acc[mb][nb][3] + bv.y };
                *(float2*)(c0 + col) = o0;
                *(float2*)(c1 + col) = o1;
            }
        }
    }
}

// ---------------- launch: fork/join overlap of rnn and GEMM -------------
extern "C" void kernel_launch(void* const* d_in, const int* in_sizes, int n_in,
                              void* d_out, int out_size) {
    const int*   X     = (const int*)  d_in[0];
    const float* h0    = (const float*)d_in[1];
    const float* W_ih  = (const float*)d_in[2];
    const float* b_ih  = (const float*)d_in[3];
    const float* W_hh  = (const float*)d_in[4];
    const float* b_hh  = (const float*)d_in[5];
    const float* W_out = (const float*)d_in[6];
    const float* b_out = (const float*)d_in[7];
    float* out    = (float*)d_out;
    float* h_last = (float*)d_out + (out_size - BATCH * HID);

    float* WihT; cudaGetSymbolAddress((void**)&WihT, g_WihT);
    float* xp;   cudaGetSymbolAddress((void**)&xp,   g_xp);
    float* Y;    cudaGetSymbolAddress((void**)&Y,    g_Y);
    float* hs;   cudaGetSymbolAddress((void**)&hs,   g_h);
    __nv_bfloat16* A2; cudaGetSymbolAddress((void**)&A2, g_A2);
    __nv_bfloat16* B2; cudaGetSymbolAddress((void**)&B2, g_B2);

    static cudaStream_t s2 = nullptr;
    static cudaEvent_t evFork, evR[NCHUNK], evJoin;
    if (!s2) {
        cudaStreamCreateWithFlags(&s2, cudaStreamNonBlocking);
        cudaEventCreateWithFlags(&evFork, cudaEventDisableTiming);
        for (int i = 0; i < NCHUNK; i++)
            cudaEventCreateWithFlags(&evR[i], cudaEventDisableTiming);
        cudaEventCreateWithFlags(&evJoin, cudaEventDisableTiming);
    }

    cudaFuncSetAttribute(rnn_chunk,
                         cudaFuncAttributeMaxDynamicSharedMemorySize, RNN_SMEM);
    cudaFuncSetAttribute(out_gemm_mma,
                         cudaFuncAttributeMaxDynamicSharedMemorySize, GEMM_SMEM);

    // main stream: embedding prep + recurrence chunks
    transpose_wih<<<dim3(VOCAB / 32, HID / 32), dim3(32, 32)>>>(W_ih, WihT);
    gather_emb<<<NTOK, HID>>>(X, b_ih, WihT, xp);
    init_h<<<BATCH, HID>>>(h0, hs);

    // fork side stream: W_out split runs under the recurrence
    cudaEventRecord(evFork, 0);
    cudaStreamWaitEvent(s2, evFork, 0);
    split_B<<<(NPAD * HID) / 256, 256, 0, s2>>>(W_out, B2);

    for (int i = 0; i < NCHUNK; i++) {
        rnn_chunk<<<BATCH, HID, RNN_SMEM>>>(hs, W_hh, b_hh, xp, Y, i * TCH);
        cudaEventRecord(evR[i], 0);
        cudaStreamWaitEvent(s2, evR[i], 0);
        split_A<<<(MCH * HID) / 256, 256, 0, s2>>>(Y, A2, i * MCH);
        out_gemm_mma<<<dim3(MCH / 128, NPAD / 128), 256, GEMM_SMEM, s2>>>(
            A2, B2, b_out, out, i * MCH);
    }
    copy_hlast<<<BATCH, HID>>>(hs, h_last);

    // join
    cudaEventRecord(evJoin, s2);
    cudaStreamWaitEvent(0, evJoin, 0);
}